// round 11
// baseline (speedup 1.0000x reference)
#include <cuda_runtime.h>
#include <cuda_fp16.h>
#include <cstdint>
#include <math.h>

// ---------------- problem constants ----------------
#define KDIM 100352          // 2048*49
#define MDIM 256             // b*t
#define NDIM 1024            // D = H*d
#define NF   2048
#define TT   32
#define SQRT_NF 45.254833995939045f
#define INV_SQRT_BN 0.9999950000374997f   // 1/sqrt(1+1e-5)

// ---------------- GEMM tiling ----------------
#define BM 256               // full M: W read exactly once
#define BN 64
#define BK 32
#define NSTAGE 4
#define SPLITK 18
#define KTILES 3136          // KDIM/BK
#define CHUNK  175           // ceil(KTILES/SPLITK); last chunk = 161 (>3 always)

// per stage: A 256 rows x 64B fp16 = 16KB ; B 64 rows x 64B fp16 = 4KB
#define A_BYTES 16384
#define STAGE_B 20480
#define SMEM_TOTAL (NSTAGE * STAGE_B)   // 81920 -> 2 CTAs/SM

// ---------------- scratch (allocation-free: device globals) ----------------
__device__ __half g_Ah[(size_t)MDIM * KDIM];
__device__ float g_part[(size_t)SPLITK * MDIM * NDIM]; // split-K partials
__device__ float g_xqn[MDIM * NDIM];                   // layernormed xq
__device__ float g_off[TT * NF];                       // beta*sqrtNF + pe[t][c]
__device__ float g_sc[NF];                             // per-channel scale
__device__ float g_q[8 * NDIM];                        // evolving q
__device__ float g_qh[8 * NDIM];                       // relu(q @ W^T + b)

// ================= prep: scales + positional encoding =================
__global__ void prep_scales(const float* __restrict__ gamma,
                            const float* __restrict__ beta) {
    int idx = blockIdx.x * 256 + threadIdx.x;      // 65536 = 32*2048
    int t = idx >> 11;
    int c = idx & (NF - 1);
    float w = __expf(-(2.0f * (float)c / (float)NF) * 9.210340371976184f); // ln(10000)
    float ang = (float)t * w;
    float pe = (c & 1) ? cosf(ang) : sinf(ang);
    g_off[idx] = beta[c] * SQRT_NF + pe;
    if (idx < NF) g_sc[idx] = gamma[idx] * SQRT_NF * INV_SQRT_BN;
}

// ========== prep A: affine -> fp16 (4 elems/thread) ==========
__global__ void prep_A(const float* __restrict__ x) {
    int n = blockIdx.y;
    int k = (blockIdx.x * 256 + threadIdx.x) * 4;   // gridDim.x = KDIM/1024 = 98
    size_t id = (size_t)n * KDIM + k;
    float4 xv = *(const float4*)(x + id);
    int to = (n & 31) * NF;
    __half2 hv[2];
    hv[0] = __floats2half2_rn(xv.x * g_sc[k / 49]       + g_off[to + k / 49],
                              xv.y * g_sc[(k + 1) / 49] + g_off[to + (k + 1) / 49]);
    hv[1] = __floats2half2_rn(xv.z * g_sc[(k + 2) / 49] + g_off[to + (k + 2) / 49],
                              xv.w * g_sc[(k + 3) / 49] + g_off[to + (k + 3) / 49]);
    *(uint2*)(g_Ah + id) = *(uint2*)hv;
}

// ================= fp16 GEMM, W converted to fp16 in B-stager =====
__device__ __forceinline__ void mma16(float* c, const uint32_t* a, const uint32_t* b) {
    asm volatile(
        "mma.sync.aligned.m16n8k16.row.col.f32.f16.f16.f32 "
        "{%0,%1,%2,%3},{%4,%5,%6,%7},{%8,%9},{%0,%1,%2,%3};"
        : "+f"(c[0]), "+f"(c[1]), "+f"(c[2]), "+f"(c[3])
        : "r"(a[0]), "r"(a[1]), "r"(a[2]), "r"(a[3]), "r"(b[0]), "r"(b[1]));
}
__device__ __forceinline__ uint32_t lds32(uint32_t a) {
    uint32_t v;
    asm volatile("ld.shared.b32 %0, [%1];" : "=r"(v) : "r"(a));
    return v;
}
__device__ __forceinline__ uint32_t packh2(float hi, float lo) {
    uint32_t d;
    asm("cvt.rn.f16x2.f32 %0, %1, %2;" : "=r"(d) : "f"(hi), "f"(lo));
    return d;
}

__global__ void __launch_bounds__(256, 2) gemm_k(const float* __restrict__ Wt) {
    extern __shared__ char smem[];
    const uint32_t sbase = (uint32_t)__cvta_generic_to_shared(smem);
    const int tid = threadIdx.x;
    const int lane = tid & 31, wid = tid >> 5;
    const int g = lane >> 2, tg = lane & 3;
    const int wm = wid >> 1, wn = wid & 1;          // 4x2 warps, tile 64x32
    const int nt = blockIdx.x, ks = blockIdx.z;
    const int k0t = ks * CHUNK;
    int nkt = KTILES - k0t; if (nkt > CHUNK) nkt = CHUNK;
    const int k0 = k0t * BK;

    // ---- A loader: 4 x 16B chunks/thread (fp16, 64B rows, slot^((row>>1)&3))
    const int rA = tid >> 2, sa4 = tid & 3;
    const uint32_t dA0 = (uint32_t)rA * 64u
        + (uint32_t)((sa4 * 16) ^ (((rA >> 1) & 3) << 4));
    const __half* pA0 = g_Ah + (size_t)rA * KDIM + k0 + sa4 * 8;

    auto ldA = [&](int s, int kt) {
        uint32_t sb = sbase + (uint32_t)s * STAGE_B;
        const __half* ap = pA0 + (size_t)kt * BK;
#pragma unroll
        for (int j = 0; j < 4; j++)
            asm volatile("cp.async.cg.shared.global [%0], [%1], 16;"
                         :: "r"(sb + dA0 + j * 4096u), "l"(ap + (size_t)j * 64 * KDIM));
        asm volatile("cp.async.commit_group;" ::: "memory");
    };

    // ---- B stager: LDG fp32 (8 floats/thread) -> cvt -> STS.128 fp16
    // B rows 64B fp16, same swizzle family as A: slot^((row>>1)&3)
    const int rB = tid >> 2, sb4 = tid & 3;
    const uint32_t dB0 = (uint32_t)A_BYTES + (uint32_t)rB * 64u
        + (uint32_t)((sb4 * 16) ^ (((rB >> 1) & 3) << 4));
    const float* pB0 = Wt + ((size_t)(nt * BN) + rB) * KDIM + k0 + sb4 * 8;

    float4 br[2][2];                               // two staged iterations
    auto ldgB = [&](float4* r, int kt) {
        const float4* p = (const float4*)(pB0 + (size_t)kt * BK);
        r[0] = p[0];
        r[1] = p[1];
    };
    auto stsB = [&](int s, const float4* r) {
        uint32_t h0 = packh2(r[0].y, r[0].x);
        uint32_t h1 = packh2(r[0].w, r[0].z);
        uint32_t h2v = packh2(r[1].y, r[1].x);
        uint32_t h3 = packh2(r[1].w, r[1].z);
        asm volatile("st.shared.v4.b32 [%0], {%1,%2,%3,%4};"
                     :: "r"(sbase + (uint32_t)s * STAGE_B + dB0),
                        "r"(h0), "r"(h1), "r"(h2v), "r"(h3) : "memory");
    };

    // ---- fragment addressing (shared col pattern for A and B) ----
    uint32_t colA[4];
#pragma unroll
    for (int jj = 0; jj < 4; jj++)
        colA[jj] = (uint32_t)(((jj ^ (g >> 1)) << 4) + tg * 4);
    uint32_t rowAm[4];
#pragma unroll
    for (int mi = 0; mi < 4; mi++)
        rowAm[mi] = (uint32_t)(wm * 64 + mi * 16 + g) * 64u;
    uint32_t rowB[4];
#pragma unroll
    for (int ni = 0; ni < 4; ni++)
        rowB[ni] = (uint32_t)A_BYTES + (uint32_t)(wn * 32 + ni * 8 + g) * 64u;

    float acc[4][4][4];
#pragma unroll
    for (int a = 0; a < 4; a++)
#pragma unroll
        for (int b = 0; b < 4; b++)
#pragma unroll
            for (int cc = 0; cc < 4; cc++) acc[a][b][cc] = 0.f;

    // ---- prologue ----
    ldA(0, 0); ldA(1, 1); ldA(2, 2);
    ldgB(br[0], 0);
    ldgB(br[1], 1);
    stsB(0, br[0]);                 // B(0) into stage 0 (visible after first sync)
    ldgB(br[0], 2);                 // B(2) (nkt >= 161 always)

    for (int kt = 0; kt < nkt; kt++) {
        if (kt + 2 < nkt)      { asm volatile("cp.async.wait_group 2;" ::: "memory"); }
        else if (kt + 1 < nkt) { asm volatile("cp.async.wait_group 1;" ::: "memory"); }
        else                   { asm volatile("cp.async.wait_group 0;" ::: "memory"); }
        __syncthreads();

        if (kt + 1 < nkt) stsB((kt + 1) & 3, br[(kt + 1) & 1]);   // B(kt+1) -> smem
        if (kt + 3 < nkt) {
            ldA((kt + 3) & 3, kt + 3);
            ldgB(br[(kt + 3) & 1], kt + 3);                        // refill freed set
        }

        uint32_t sb = sbase + (uint32_t)(kt & 3) * STAGE_B;
#pragma unroll
        for (int ks2 = 0; ks2 < 2; ks2++) {          // 2 x k16 per BK=32
            const int j0 = ks2 * 2;
            uint32_t ah[4][4];
#pragma unroll
            for (int mi = 0; mi < 4; mi++) {
                uint32_t r0a = sb + rowAm[mi];
                uint32_t r1a = r0a + 512u;           // +8 rows * 64B
                ah[mi][0] = lds32(r0a + colA[j0]);     ah[mi][1] = lds32(r1a + colA[j0]);
                ah[mi][2] = lds32(r0a + colA[j0 + 1]); ah[mi][3] = lds32(r1a + colA[j0 + 1]);
            }
            uint32_t bh[4][2];
#pragma unroll
            for (int ni = 0; ni < 4; ni++) {
                uint32_t rbb = sb + rowB[ni];
                bh[ni][0] = lds32(rbb + colA[j0]);
                bh[ni][1] = lds32(rbb + colA[j0 + 1]);
            }
#pragma unroll
            for (int mi = 0; mi < 4; mi++)
#pragma unroll
                for (int ni = 0; ni < 4; ni++)
                    mma16(acc[mi][ni], ah[mi], bh[ni]);
        }
    }

    // ---- epilogue: write split-K partials ----
    float* outp = g_part + (size_t)ks * MDIM * NDIM;
#pragma unroll
    for (int mi = 0; mi < 4; mi++) {
        int r = wm * 64 + mi * 16 + g;
#pragma unroll
        for (int ni = 0; ni < 4; ni++) {
            int c = nt * BN + wn * 32 + ni * 8 + 2 * tg;
            *(float2*)&outp[(size_t)r * NDIM + c] =
                make_float2(acc[mi][ni][0], acc[mi][ni][1]);
            *(float2*)&outp[(size_t)(r + 8) * NDIM + c] =
                make_float2(acc[mi][ni][2], acc[mi][ni][3]);
        }
    }
}

// ============ split-K reduce + ReLU + LayerNorm(ddof=1) over D ============
__global__ void reduce_ln() {
    int row = blockIdx.x, tid = threadIdx.x;
    float v[4], s = 0.f, ss = 0.f;
#pragma unroll
    for (int j = 0; j < 4; j++) {
        int col = tid + j * 256;
        float a = 0.f;
#pragma unroll
        for (int sk = 0; sk < SPLITK; sk++)
            a += g_part[((size_t)sk * MDIM + row) * NDIM + col];
        a = fmaxf(a, 0.f);
        v[j] = a; s += a; ss += a * a;
    }
    __shared__ float r1[8], r2[8];
#pragma unroll
    for (int o = 16; o > 0; o >>= 1) {
        s  += __shfl_xor_sync(0xffffffffu, s, o);
        ss += __shfl_xor_sync(0xffffffffu, ss, o);
    }
    if ((tid & 31) == 0) { r1[tid >> 5] = s; r2[tid >> 5] = ss; }
    __syncthreads();
    if (tid == 0) {
        float S = 0.f, SS = 0.f;
        for (int w = 0; w < 8; w++) { S += r1[w]; SS += r2[w]; }
        r1[0] = S; r2[0] = SS;
    }
    __syncthreads();
    float mean = r1[0] * (1.f / 1024.f);
    float var  = (r2[0] - 1024.f * mean * mean) * (1.f / 1023.f);
    float inv  = 1.f / (sqrtf(fmaxf(var, 0.f)) + 1e-6f);
#pragma unroll
    for (int j = 0; j < 4; j++)
        g_xqn[row * NDIM + tid + j * 256] = (v[j] - mean) * inv;
}

// ============ qh = relu(q @ qlin_w[i].T + qlin_b[i]), 128 blocks ============
__global__ void __launch_bounds__(256) gemv_k(
    const float* __restrict__ qlw, const float* __restrict__ qlb,
    const float* __restrict__ qsrc, int qrowstride, int qoff, int i)
{
    const int b = blockIdx.y, c = blockIdx.x;     // grid (16, 8)
    const int tid = threadIdx.x;
    const int o = c * 64 + (tid >> 2);            // output index
    const int part = tid & 3;

    __shared__ float qS[1024];
    const float* qp = qsrc + (size_t)b * qrowstride + qoff;
#pragma unroll
    for (int j = tid; j < 1024; j += 256) qS[j] = qp[j];
    __syncthreads();

    const float4* W4 = (const float4*)(qlw + ((size_t)i * 1024 + o) * 1024 + part * 256);
    const float* qb = qS + part * 256;
    float acc = 0.f;
#pragma unroll 8
    for (int j = 0; j < 64; j++) {
        float4 w = W4[j];
        acc += w.x * qb[j * 4] + w.y * qb[j * 4 + 1]
             + w.z * qb[j * 4 + 2] + w.w * qb[j * 4 + 3];
    }
    acc += __shfl_xor_sync(0xffffffffu, acc, 1);
    acc += __shfl_xor_sync(0xffffffffu, acc, 2);
    if (part == 0) g_qh[b * 1024 + o] = fmaxf(acc + qlb[i * 1024 + o], 0.f);
}

// ============ attention rest: softmax + AV + norms + FFN ============
__global__ void __launch_bounds__(1024) rest_k(
    const float* __restrict__ n1a, const float* __restrict__ n1b,
    const float* __restrict__ n2a, const float* __restrict__ n2b,
    const float* __restrict__ fw1, const float* __restrict__ fb1,
    const float* __restrict__ fw2, const float* __restrict__ fb2,
    int i, int last, float* __restrict__ out)
{
    const int b = blockIdx.x, tid = threadIdx.x;
    const int h = tid >> 6, d = tid & 63;     // 16 x 64
    const int h2 = tid >> 5, t2 = tid & 31;   // 16 x 32 (tid < 512)

    __shared__ float qhS[1024], q_S[1024], zS[1024];
    __shared__ float scS[16 * 32], hidS[16 * 32];
    __shared__ float muS[16], isdS[16], redA[32];

    qhS[tid] = g_qh[b * 1024 + tid];
    __syncthreads();

    if (tid < 512) {
        const float* khp = g_xqn + (b * 32 + t2) * NDIM + h2 * 64;
        const float* qp  = qhS + h2 * 64;
        float dot = 0.f;
#pragma unroll
        for (int dd = 0; dd < 64; dd++) dot += qp[dd] * khp[dd];
        dot *= 0.125f;
        float m = dot;
#pragma unroll
        for (int o = 16; o > 0; o >>= 1) m = fmaxf(m, __shfl_xor_sync(0xffffffffu, m, o));
        float e = __expf(dot - m);
        float sum = e;
#pragma unroll
        for (int o = 16; o > 0; o >>= 1) sum += __shfl_xor_sync(0xffffffffu, sum, o);
        scS[h2 * 32 + t2] = e / sum;
    }
    __syncthreads();

    {
        float a = 0.f;
        const float* vb = g_xqn + (size_t)(b * 32) * NDIM + h * 64 + d;
#pragma unroll
        for (int tt = 0; tt < 32; tt++) a += scS[h * 32 + tt] * vb[tt * NDIM];
        float z = a + qhS[tid];
        zS[tid] = z;
        __syncthreads();
        if (tid < 16) {
            float s = 0.f, ssum = 0.f;
            for (int dd = 0; dd < 64; dd++) {
                float v = zS[tid * 64 + dd]; s += v; ssum += v * v;
            }
            float mu = s * (1.f / 64.f);
            float var = (ssum - 64.f * mu * mu) * (1.f / 63.f);
            muS[tid] = mu;
            isdS[tid] = 1.f / (sqrtf(fmaxf(var, 0.f)) + 1e-6f);
        }
        __syncthreads();
        q_S[tid] = n1a[(i * 16 + h) * 64 + d] * (zS[tid] - muS[h]) * isdS[h]
                 + n1b[(i * 16 + h) * 64 + d];
    }
    __syncthreads();

    if (tid < 512) {
        const float* w1 = fw1 + ((size_t)(i * 16 + h2) * 32 + t2) * 64;
        float acc = fb1[(i * 16 + h2) * 32 + t2];
#pragma unroll
        for (int dd = 0; dd < 64; dd++) acc += q_S[h2 * 64 + dd] * w1[dd];
        hidS[h2 * 32 + t2] = fmaxf(acc, 0.f);
    }
    __syncthreads();

    float qv;
    {
        const float* w2 = fw2 + ((size_t)(i * 16 + h) * 64 + d) * 32;
        float acc = fb2[(i * 16 + h) * 64 + d];
#pragma unroll
        for (int ff = 0; ff < 32; ff++) acc += hidS[h * 32 + ff] * w2[ff];
        float z = q_S[tid] + acc;
        __syncthreads();
        zS[tid] = z;
        __syncthreads();
        if (tid < 16) {
            float s = 0.f, ssum = 0.f;
            for (int dd = 0; dd < 64; dd++) {
                float v = zS[tid * 64 + dd]; s += v; ssum += v * v;
            }
            float mu = s * (1.f / 64.f);
            float var = (ssum - 64.f * mu * mu) * (1.f / 63.f);
            muS[tid] = mu;
            isdS[tid] = 1.f / (sqrtf(fmaxf(var, 0.f)) + 1e-6f);
        }
        __syncthreads();
        qv = n2a[(i * 16 + h) * 64 + d] * (zS[tid] - muS[h]) * isdS[h]
           + n2b[(i * 16 + h) * 64 + d];
    }

    if (!last) {
        g_q[b * 1024 + tid] = qv;
        return;
    }

    float ssq = qv * qv;
#pragma unroll
    for (int o = 16; o > 0; o >>= 1) ssq += __shfl_xor_sync(0xffffffffu, ssq, o);
    if ((tid & 31) == 0) redA[tid >> 5] = ssq;
    __syncthreads();
    if (tid < 32) {
        float s2 = redA[tid];
#pragma unroll
        for (int o = 16; o > 0; o >>= 1) s2 += __shfl_xor_sync(0xffffffffu, s2, o);
        if (tid == 0) redA[0] = s2;
    }
    __syncthreads();
    float nrm = sqrtf(redA[0]);
    out[b * 1024 + tid] = qv / fmaxf(nrm, 1e-12f);
}

// ================= launch =================
extern "C" void kernel_launch(void* const* d_in, const int* in_sizes, int n_in,
                              void* d_out, int out_size) {
    const float* x     = (const float*)d_in[0];
    const float* gamma = (const float*)d_in[1];
    const float* beta  = (const float*)d_in[2];
    const float* qpr   = (const float*)d_in[3];
    const float* qlw   = (const float*)d_in[4];
    const float* qlb   = (const float*)d_in[5];
    const float* n1a   = (const float*)d_in[6];
    const float* n1b   = (const float*)d_in[7];
    const float* n2a   = (const float*)d_in[8];
    const float* n2b   = (const float*)d_in[9];
    const float* fw1   = (const float*)d_in[10];
    const float* fb1   = (const float*)d_in[11];
    const float* fw2   = (const float*)d_in[12];
    const float* fb2   = (const float*)d_in[13];
    float* out = (float*)d_out;

    prep_scales<<<256, 256>>>(gamma, beta);
    prep_A<<<dim3(98, MDIM), 256>>>(x);

    cudaFuncSetAttribute(gemm_k, cudaFuncAttributeMaxDynamicSharedMemorySize, SMEM_TOTAL);
    gemm_k<<<dim3(NDIM / BN, 1, SPLITK), 256, SMEM_TOTAL>>>(qpr);

    reduce_ln<<<MDIM, 256>>>();

    float* g_xqn_p = nullptr;
    float* g_q_p = nullptr;
    cudaGetSymbolAddress((void**)&g_xqn_p, g_xqn);
    cudaGetSymbolAddress((void**)&g_q_p, g_q);

    for (int i = 0; i < 3; i++) {
        if (i == 0)
            gemv_k<<<dim3(16, 8), 256>>>(qlw, qlb, g_xqn_p, 32 * NDIM, 16 * NDIM, 0);
        else
            gemv_k<<<dim3(16, 8), 256>>>(qlw, qlb, g_q_p, NDIM, 0, i);
        rest_k<<<8, 1024>>>(n1a, n1b, n2a, n2b, fw1, fb1, fw2, fb2,
                            i, (i == 2) ? 1 : 0, out);
    }
}

// round 12
// speedup vs baseline: 1.2016x; 1.2016x over previous
#include <cuda_runtime.h>
#include <cuda_fp16.h>
#include <cstdint>
#include <math.h>

// ---------------- problem constants ----------------
#define KDIM 100352          // 2048*49
#define MDIM 256             // b*t
#define NDIM 1024            // D = H*d
#define NF   2048
#define TT   32
#define SQRT_NF 45.254833995939045f
#define INV_SQRT_BN 0.9999950000374997f   // 1/sqrt(1+1e-5)

// ---------------- GEMM tiling (round-8 champion config) ----------------
#define BM 256               // full M: W read exactly once
#define BN 64
#define BK 64
#define SPLITK 18
#define KTILES 1568          // KDIM/BK
#define CHUNK  88            // ceil(KTILES/SPLITK); last chunk = 72

// per stage: A 256 rows x 128B fp16 = 32KB ; B 64 rows x 256B fp32 = 16KB
#define A_BYTES 32768
#define STAGE_B 49152
#define SMEM_TOTAL (2 * STAGE_B)   // 98304

// ---------------- scratch (allocation-free: device globals) ----------------
__device__ __half g_Ah[(size_t)MDIM * KDIM];
__device__ float g_part[(size_t)SPLITK * MDIM * NDIM]; // split-K partials
__device__ float g_xqn[MDIM * NDIM];                   // layernormed xq
__device__ float g_off[TT * NF];                       // beta*sqrtNF + pe[t][c]
__device__ float g_sc[NF];                             // per-channel scale
__device__ float g_q[8 * NDIM];                        // evolving q
__device__ float g_qh[8 * NDIM];                       // relu(q @ W^T + b)

// ================= prep: positional-encoding offsets =================
__global__ void prep_off(const float* __restrict__ beta) {
    int idx = blockIdx.x * 256 + threadIdx.x;      // 65536 = 32*2048
    int t = idx >> 11;
    int c = idx & (NF - 1);
    float w = __expf(-(2.0f * (float)c / (float)NF) * 9.210340371976184f); // ln(10000)
    float ang = (float)t * w;
    float pe = (c & 1) ? cosf(ang) : sinf(ang);
    g_off[idx] = beta[c] * SQRT_NF + pe;
}

// ================= prep: per-channel scales (also the launch-order pad
// that places gemm_k at the ncu-captured slot) =================
__global__ void prep_sc(const float* __restrict__ gamma) {
    int c = blockIdx.x * 256 + threadIdx.x;        // 2048
    g_sc[c] = gamma[c] * SQRT_NF * INV_SQRT_BN;
}

// ========== prep A: affine -> fp16 (4 elems/thread) ==========
__global__ void prep_A(const float* __restrict__ x) {
    int n = blockIdx.y;
    int k = (blockIdx.x * 256 + threadIdx.x) * 4;   // gridDim.x = KDIM/1024 = 98
    size_t id = (size_t)n * KDIM + k;
    float4 xv = __ldcs((const float4*)(x + id));
    int to = (n & 31) * NF;
    __half2 hv[2];
    hv[0] = __floats2half2_rn(xv.x * g_sc[k / 49]       + g_off[to + k / 49],
                              xv.y * g_sc[(k + 1) / 49] + g_off[to + (k + 1) / 49]);
    hv[1] = __floats2half2_rn(xv.z * g_sc[(k + 2) / 49] + g_off[to + (k + 2) / 49],
                              xv.w * g_sc[(k + 3) / 49] + g_off[to + (k + 3) / 49]);
    *(uint2*)(g_Ah + id) = *(uint2*)hv;
}

// ================= fp16 GEMM, W kept fp32 in smem, cvt at fragment time =====
__device__ __forceinline__ void mma16(float* c, const uint32_t* a, const uint32_t* b) {
    asm volatile(
        "mma.sync.aligned.m16n8k16.row.col.f32.f16.f16.f32 "
        "{%0,%1,%2,%3},{%4,%5,%6,%7},{%8,%9},{%0,%1,%2,%3};"
        : "+f"(c[0]), "+f"(c[1]), "+f"(c[2]), "+f"(c[3])
        : "r"(a[0]), "r"(a[1]), "r"(a[2]), "r"(a[3]), "r"(b[0]), "r"(b[1]));
}
__device__ __forceinline__ uint32_t lds32(uint32_t a) {
    uint32_t v;
    asm volatile("ld.shared.b32 %0, [%1];" : "=r"(v) : "r"(a));
    return v;
}
__device__ __forceinline__ float2 lds64(uint32_t a) {
    float2 v;
    asm volatile("ld.shared.v2.f32 {%0,%1}, [%2];" : "=f"(v.x), "=f"(v.y) : "r"(a));
    return v;
}
__device__ __forceinline__ uint32_t packh2(float hi, float lo) {
    uint32_t d;
    asm("cvt.rn.f16x2.f32 %0, %1, %2;" : "=r"(d) : "f"(hi), "f"(lo));
    return d;
}

__global__ void __launch_bounds__(256, 2) gemm_k(const float* __restrict__ Wt) {
    extern __shared__ char smem[];
    const uint32_t sbase = (uint32_t)__cvta_generic_to_shared(smem);
    const int tid = threadIdx.x;
    const int lane = tid & 31, wid = tid >> 5;
    const int g = lane >> 2, tg = lane & 3;
    const int wm = wid >> 1, wn = wid & 1;          // 4x2 warps, tile 64x32
    const int nt = blockIdx.x, ks = blockIdx.z;
    const int k0t = ks * CHUNK;
    int nkt = KTILES - k0t; if (nkt > CHUNK) nkt = CHUNK;
    const int k0 = k0t * BK;

    // ---- A loader: 8 x 16B chunks/thread (fp16, 128B rows, 16B-granule swizzle)
    const int rA = tid >> 3, pa = tid & 7;
    const uint32_t dA0 = (uint32_t)rA * 128u + (uint32_t)((pa * 16) ^ ((rA & 7) << 4));
    const __half* pA0 = g_Ah + (size_t)rA * KDIM + k0 + pa * 8;

    // ---- B loader: 4 x 16B chunks/thread (fp32, 256B rows, 32B-granule swizzle)
    const int rB = tid >> 2, chB = tid & 3;
    uint32_t dB[4];
#pragma unroll
    for (int u = 0; u < 4; u++)
        dB[u] = (uint32_t)A_BYTES + (uint32_t)rB * 256u
              + (uint32_t)((chB * 16 + 64 * u) ^ ((rB & 7) << 5));
    const float* pB0 = Wt + ((size_t)(nt * BN) + rB) * KDIM + k0 + chB * 4;

    auto ldAB = [&](int s, int kt) {
        uint32_t sb = sbase + (uint32_t)s * STAGE_B;
        const __half* ap = pA0 + (size_t)kt * BK;
#pragma unroll
        for (int j = 0; j < 8; j++)
            asm volatile("cp.async.cg.shared.global [%0], [%1], 16;"
                         :: "r"(sb + dA0 + j * 4096u), "l"(ap + (size_t)j * 32 * KDIM));
        const float* bp = pB0 + (size_t)kt * BK;
#pragma unroll
        for (int u = 0; u < 4; u++)
            asm volatile("cp.async.cg.shared.global [%0], [%1], 16;"
                         :: "r"(sb + dB[u]), "l"(bp + u * 16));
        asm volatile("cp.async.commit_group;" ::: "memory");
    };

    // ---- fragment addressing ----
    uint32_t col[8];
#pragma unroll
    for (int jj = 0; jj < 8; jj++) col[jj] = (uint32_t)(((jj ^ g) << 4) + tg * 4);
    uint32_t rowA[4][2], rowB[4];
#pragma unroll
    for (int mi = 0; mi < 4; mi++) {
        rowA[mi][0] = (uint32_t)(wm * 64 + mi * 16 + g) * 128u;
        rowA[mi][1] = rowA[mi][0] + 8u * 128u;
    }
#pragma unroll
    for (int ni = 0; ni < 4; ni++)
        rowB[ni] = (uint32_t)A_BYTES + (uint32_t)(wn * 32 + ni * 8 + g) * 256u;
    const uint32_t gkey = (uint32_t)(g << 5);       // B swizzle key (row&7 == g)

    float acc[4][4][4];
#pragma unroll
    for (int a = 0; a < 4; a++)
#pragma unroll
        for (int b = 0; b < 4; b++)
#pragma unroll
            for (int cc = 0; cc < 4; cc++) acc[a][b][cc] = 0.f;

    // ---- 2-stage pipeline ----
    ldAB(0, 0);
    ldAB(1, 1);

    for (int kt = 0; kt < nkt; kt++) {
        const int s = kt & 1;
        if (kt + 1 < nkt) { asm volatile("cp.async.wait_group 1;" ::: "memory"); }
        else              { asm volatile("cp.async.wait_group 0;" ::: "memory"); }
        __syncthreads();

        uint32_t sb = sbase + (uint32_t)s * STAGE_B;
#pragma unroll
        for (int ks2 = 0; ks2 < 4; ks2++) {          // 4 x k16 per BK=64
            const int j0 = ks2 * 2;
            uint32_t ah[4][4];
#pragma unroll
            for (int mi = 0; mi < 4; mi++) {
                uint32_t r0a = sb + rowA[mi][0], r1a = sb + rowA[mi][1];
                ah[mi][0] = lds32(r0a + col[j0]);     ah[mi][1] = lds32(r1a + col[j0]);
                ah[mi][2] = lds32(r0a + col[j0 + 1]); ah[mi][3] = lds32(r1a + col[j0 + 1]);
            }
            const uint32_t off0 = (uint32_t)(64 * ks2 + 8 * tg) ^ gkey;
            const uint32_t off1 = off0 ^ 32u;
            uint32_t bh[4][2];
#pragma unroll
            for (int ni = 0; ni < 4; ni++) {
                uint32_t rbb = sb + rowB[ni];
                float2 v0 = lds64(rbb + off0);
                float2 v1 = lds64(rbb + off1);
                bh[ni][0] = packh2(v0.y, v0.x);
                bh[ni][1] = packh2(v1.y, v1.x);
            }
#pragma unroll
            for (int mi = 0; mi < 4; mi++)
#pragma unroll
                for (int ni = 0; ni < 4; ni++)
                    mma16(acc[mi][ni], ah[mi], bh[ni]);
        }

        if (kt + 2 < nkt) {
            __syncthreads();                 // stage s consumed by all warps
            ldAB(s, kt + 2);
        }
    }

    // ---- epilogue: write split-K partials ----
    float* outp = g_part + (size_t)ks * MDIM * NDIM;
#pragma unroll
    for (int mi = 0; mi < 4; mi++) {
        int r = wm * 64 + mi * 16 + g;
#pragma unroll
        for (int ni = 0; ni < 4; ni++) {
            int c = nt * BN + wn * 32 + ni * 8 + 2 * tg;
            *(float2*)&outp[(size_t)r * NDIM + c] =
                make_float2(acc[mi][ni][0], acc[mi][ni][1]);
            *(float2*)&outp[(size_t)(r + 8) * NDIM + c] =
                make_float2(acc[mi][ni][2], acc[mi][ni][3]);
        }
    }
}

// ============ split-K reduce + ReLU + LayerNorm(ddof=1) over D ============
__global__ void reduce_ln() {
    int row = blockIdx.x, tid = threadIdx.x;
    float v[4], s = 0.f, ss = 0.f;
#pragma unroll
    for (int j = 0; j < 4; j++) {
        int col = tid + j * 256;
        float a = 0.f;
#pragma unroll
        for (int sk = 0; sk < SPLITK; sk++)
            a += g_part[((size_t)sk * MDIM + row) * NDIM + col];
        a = fmaxf(a, 0.f);
        v[j] = a; s += a; ss += a * a;
    }
    __shared__ float r1[8], r2[8];
#pragma unroll
    for (int o = 16; o > 0; o >>= 1) {
        s  += __shfl_xor_sync(0xffffffffu, s, o);
        ss += __shfl_xor_sync(0xffffffffu, ss, o);
    }
    if ((tid & 31) == 0) { r1[tid >> 5] = s; r2[tid >> 5] = ss; }
    __syncthreads();
    if (tid == 0) {
        float S = 0.f, SS = 0.f;
        for (int w = 0; w < 8; w++) { S += r1[w]; SS += r2[w]; }
        r1[0] = S; r2[0] = SS;
    }
    __syncthreads();
    float mean = r1[0] * (1.f / 1024.f);
    float var  = (r2[0] - 1024.f * mean * mean) * (1.f / 1023.f);
    float inv  = 1.f / (sqrtf(fmaxf(var, 0.f)) + 1e-6f);
#pragma unroll
    for (int j = 0; j < 4; j++)
        g_xqn[row * NDIM + tid + j * 256] = (v[j] - mean) * inv;
}

// ============ qh = relu(q @ qlin_w[i].T + qlin_b[i]), 128 blocks ============
__global__ void __launch_bounds__(256) gemv_k(
    const float* __restrict__ qlw, const float* __restrict__ qlb,
    const float* __restrict__ qsrc, int qrowstride, int qoff, int i)
{
    const int b = blockIdx.y, c = blockIdx.x;     // grid (16, 8)
    const int tid = threadIdx.x;
    const int o = c * 64 + (tid >> 2);            // output index
    const int part = tid & 3;

    __shared__ float qS[1024];
    const float* qp = qsrc + (size_t)b * qrowstride + qoff;
#pragma unroll
    for (int j = tid; j < 1024; j += 256) qS[j] = qp[j];
    __syncthreads();

    const float4* W4 = (const float4*)(qlw + ((size_t)i * 1024 + o) * 1024 + part * 256);
    const float* qb = qS + part * 256;
    float acc = 0.f;
#pragma unroll 8
    for (int j = 0; j < 64; j++) {
        float4 w = W4[j];
        acc += w.x * qb[j * 4] + w.y * qb[j * 4 + 1]
             + w.z * qb[j * 4 + 2] + w.w * qb[j * 4 + 3];
    }
    acc += __shfl_xor_sync(0xffffffffu, acc, 1);
    acc += __shfl_xor_sync(0xffffffffu, acc, 2);
    if (part == 0) g_qh[b * 1024 + o] = fmaxf(acc + qlb[i * 1024 + o], 0.f);
}

// ============ attention rest: softmax + AV + norms + FFN ============
__global__ void __launch_bounds__(1024) rest_k(
    const float* __restrict__ n1a, const float* __restrict__ n1b,
    const float* __restrict__ n2a, const float* __restrict__ n2b,
    const float* __restrict__ fw1, const float* __restrict__ fb1,
    const float* __restrict__ fw2, const float* __restrict__ fb2,
    int i, int last, float* __restrict__ out)
{
    const int b = blockIdx.x, tid = threadIdx.x;
    const int h = tid >> 6, d = tid & 63;     // 16 x 64
    const int h2 = tid >> 5, t2 = tid & 31;   // 16 x 32 (tid < 512)

    __shared__ float qhS[1024], q_S[1024], zS[1024];
    __shared__ float scS[16 * 32], hidS[16 * 32];
    __shared__ float muS[16], isdS[16], redA[32];

    qhS[tid] = g_qh[b * 1024 + tid];
    __syncthreads();

    if (tid < 512) {
        const float* khp = g_xqn + (b * 32 + t2) * NDIM + h2 * 64;
        const float* qp  = qhS + h2 * 64;
        float dot = 0.f;
#pragma unroll
        for (int dd = 0; dd < 64; dd++) dot += qp[dd] * khp[dd];
        dot *= 0.125f;
        float m = dot;
#pragma unroll
        for (int o = 16; o > 0; o >>= 1) m = fmaxf(m, __shfl_xor_sync(0xffffffffu, m, o));
        float e = __expf(dot - m);
        float sum = e;
#pragma unroll
        for (int o = 16; o > 0; o >>= 1) sum += __shfl_xor_sync(0xffffffffu, sum, o);
        scS[h2 * 32 + t2] = e / sum;
    }
    __syncthreads();

    {
        float a = 0.f;
        const float* vb = g_xqn + (size_t)(b * 32) * NDIM + h * 64 + d;
#pragma unroll
        for (int tt = 0; tt < 32; tt++) a += scS[h * 32 + tt] * vb[tt * NDIM];
        float z = a + qhS[tid];
        zS[tid] = z;
        __syncthreads();
        if (tid < 16) {
            float s = 0.f, ssum = 0.f;
            for (int dd = 0; dd < 64; dd++) {
                float v = zS[tid * 64 + dd]; s += v; ssum += v * v;
            }
            float mu = s * (1.f / 64.f);
            float var = (ssum - 64.f * mu * mu) * (1.f / 63.f);
            muS[tid] = mu;
            isdS[tid] = 1.f / (sqrtf(fmaxf(var, 0.f)) + 1e-6f);
        }
        __syncthreads();
        q_S[tid] = n1a[(i * 16 + h) * 64 + d] * (zS[tid] - muS[h]) * isdS[h]
                 + n1b[(i * 16 + h) * 64 + d];
    }
    __syncthreads();

    if (tid < 512) {
        const float* w1 = fw1 + ((size_t)(i * 16 + h2) * 32 + t2) * 64;
        float acc = fb1[(i * 16 + h2) * 32 + t2];
#pragma unroll
        for (int dd = 0; dd < 64; dd++) acc += q_S[h2 * 64 + dd] * w1[dd];
        hidS[h2 * 32 + t2] = fmaxf(acc, 0.f);
    }
    __syncthreads();

    float qv;
    {
        const float* w2 = fw2 + ((size_t)(i * 16 + h) * 64 + d) * 32;
        float acc = fb2[(i * 16 + h) * 64 + d];
#pragma unroll
        for (int ff = 0; ff < 32; ff++) acc += hidS[h * 32 + ff] * w2[ff];
        float z = q_S[tid] + acc;
        __syncthreads();
        zS[tid] = z;
        __syncthreads();
        if (tid < 16) {
            float s = 0.f, ssum = 0.f;
            for (int dd = 0; dd < 64; dd++) {
                float v = zS[tid * 64 + dd]; s += v; ssum += v * v;
            }
            float mu = s * (1.f / 64.f);
            float var = (ssum - 64.f * mu * mu) * (1.f / 63.f);
            muS[tid] = mu;
            isdS[tid] = 1.f / (sqrtf(fmaxf(var, 0.f)) + 1e-6f);
        }
        __syncthreads();
        qv = n2a[(i * 16 + h) * 64 + d] * (zS[tid] - muS[h]) * isdS[h]
           + n2b[(i * 16 + h) * 64 + d];
    }

    if (!last) {
        g_q[b * 1024 + tid] = qv;
        return;
    }

    float ssq = qv * qv;
#pragma unroll
    for (int o = 16; o > 0; o >>= 1) ssq += __shfl_xor_sync(0xffffffffu, ssq, o);
    if ((tid & 31) == 0) redA[tid >> 5] = ssq;
    __syncthreads();
    if (tid < 32) {
        float s2 = redA[tid];
#pragma unroll
        for (int o = 16; o > 0; o >>= 1) s2 += __shfl_xor_sync(0xffffffffu, s2, o);
        if (tid == 0) redA[0] = s2;
    }
    __syncthreads();
    float nrm = sqrtf(redA[0]);
    out[b * 1024 + tid] = qv / fmaxf(nrm, 1e-12f);
}

// ================= launch =================
extern "C" void kernel_launch(void* const* d_in, const int* in_sizes, int n_in,
                              void* d_out, int out_size) {
    const float* x     = (const float*)d_in[0];
    const float* gamma = (const float*)d_in[1];
    const float* beta  = (const float*)d_in[2];
    const float* qpr   = (const float*)d_in[3];
    const float* qlw   = (const float*)d_in[4];
    const float* qlb   = (const float*)d_in[5];
    const float* n1a   = (const float*)d_in[6];
    const float* n1b   = (const float*)d_in[7];
    const float* n2a   = (const float*)d_in[8];
    const float* n2b   = (const float*)d_in[9];
    const float* fw1   = (const float*)d_in[10];
    const float* fb1   = (const float*)d_in[11];
    const float* fw2   = (const float*)d_in[12];
    const float* fb2   = (const float*)d_in[13];
    float* out = (float*)d_out;

    prep_off<<<256, 256>>>(beta);          // launch 0
    prep_sc<<<8, 256>>>(gamma);            // launch 1
    prep_A<<<dim3(98, MDIM), 256>>>(x);    // launch 2

    cudaFuncSetAttribute(gemm_k, cudaFuncAttributeMaxDynamicSharedMemorySize, SMEM_TOTAL);
    gemm_k<<<dim3(NDIM / BN, 1, SPLITK), 256, SMEM_TOTAL>>>(qpr);  // launch 3 (profiled)

    reduce_ln<<<MDIM, 256>>>();

    float* g_xqn_p = nullptr;
    float* g_q_p = nullptr;
    cudaGetSymbolAddress((void**)&g_xqn_p, g_xqn);
    cudaGetSymbolAddress((void**)&g_q_p, g_q);

    for (int i = 0; i < 3; i++) {
        if (i == 0)
            gemv_k<<<dim3(16, 8), 256>>>(qlw, qlb, g_xqn_p, 32 * NDIM, 16 * NDIM, 0);
        else
            gemv_k<<<dim3(16, 8), 256>>>(qlw, qlb, g_q_p, NDIM, 0, i);
        rest_k<<<8, 1024>>>(n1a, n1b, n2a, n2b, fw1, fb1, fw2, fb2,
                            i, (i == 2) ? 1 : 0, out);
    }
}